// round 9
// baseline (speedup 1.0000x reference)
#include <cuda_runtime.h>
#include <cuda_fp16.h>
#include <cstdint>
#include <cstddef>

#define BB 64
#define TT 1024
#define DD 512
#define HH 1024
#define KK 1536            // D + H (fused [x|h] operand)
#define NCTA 128           // persistent CTAs, 1 per SM, all co-resident
#define THREADS 128        // 4 warps: one m16 tile each
#define NCOL 32            // gate columns per CTA = 4 gates x 8 hidden units
#define KC 384             // K-chunk for A staging
#define NCHUNK 4           // KK / KC
#define NKT 96             // total k16 tiles (KK/16)
#define AROW 392           // KC + 8 pad halves (784B rows: conflict-free ldmatrix)
#define WS_HALVES (KK * NCOL)               // 49,152 halves = 96 KB, fragment-major
#define SMEM_BYTES ((WS_HALVES + 2*BB*AROW) * 2)   // 198,656 B
#define NGRP 8             // split progress counters (8 groups of 16 CTAs)

// Scratch (static __device__ globals: no allocation anywhere)
__device__ __half   g_xh[(size_t)BB * TT * DD];    // fp16 inputs, layout [B][T][D]
__device__ __half   g_hbuf[2][BB][HH];             // double-buffered hidden state, fp16
struct CtrSlot { unsigned v; unsigned pad[31]; };   // one 128B line per counter
__device__ CtrSlot  g_ctrs[NGRP];                   // split progress counters

// ---------------------------------------------------------------------------
// fp32 -> fp16 input conversion
// ---------------------------------------------------------------------------
__global__ void cvt_kernel(const float* __restrict__ x, __half2* __restrict__ y, int n4) {
    int i = blockIdx.x * blockDim.x + threadIdx.x;
    int stride = gridDim.x * blockDim.x;
    const float4* x4 = (const float4*)x;
    for (; i < n4; i += stride) {
        float4 v = x4[i];
        y[2 * i]     = __floats2half2_rn(v.x, v.y);
        y[2 * i + 1] = __floats2half2_rn(v.z, v.w);
    }
}

__device__ __forceinline__ float sigf(float x) {
    return __fdividef(1.0f, 1.0f + __expf(-x));
}
__device__ __forceinline__ float tanhfast(float x) {
    return 1.0f - __fdividef(2.0f, 1.0f + __expf(2.0f * x));
}

__device__ __forceinline__ void cp16(uint32_t dst, const void* src) {
    asm volatile("cp.async.cg.shared.global [%0], [%1], 16;\n" :: "r"(dst), "l"(src));
}

// ---------------------------------------------------------------------------
// Persistent fused LSTM kernel
// ---------------------------------------------------------------------------
extern __shared__ __half smem_dyn[];

__global__ void __launch_bounds__(THREADS, 1)
lstm_kernel(const float* __restrict__ Wx, const float* __restrict__ Wh,
            const float* __restrict__ bias, float* __restrict__ out)
{
    __half* Ws = smem_dyn;                    // fragment-major resident weights (96 KB)
    __half* Ab = smem_dyn + WS_HALVES;        // 2 x [BB][AROW] A staging buffers

    const int tid  = threadIdx.x;
    const int lane = tid & 31;
    const int warp = tid >> 5;
    const int cta  = blockIdx.x;
    const int j0   = cta * 8;                 // this CTA's hidden-unit base

    // ---- one-time: load weight slice in mma-fragment-major layout ----
    // Ws[kt][half][lane][8 halves]: lane (q=lane&3, nr=lane>>2) holds, for
    // gates tg=2*half+sub, the b0/b1 fragment halves k in {2q,2q+1,2q+8,2q+9}.
    // index = ((kt*2+half)*32 + nr*4+q)*8 + sub*4 + slot,
    //   q = (j&7)>>1, slot = (j&1) + ((j>>3)<<1), j = k&15.
    // One LDS.128 per (kt,half) then yields both gates' fragments. Bank-safe:
    // addr = lane*16B -> each 8-lane phase covers words 4L..4L+3 = all 32 banks.
    for (int idx = tid; idx < KK * NCOL; idx += THREADS) {
        int k = idx >> 5;
        int n = idx & 31;
        int col = (n >> 3) * HH + j0 + (n & 7);
        float w = (k < DD) ? Wx[(size_t)k * (4 * HH) + col]
                           : Wh[(size_t)(k - DD) * (4 * HH) + col];
        int kt   = k >> 4;
        int j    = k & 15;
        int q    = (j & 7) >> 1;
        int slot = (j & 1) + ((j >> 3) << 1);
        int tg   = n >> 3;
        int half = tg >> 1;
        int sub  = tg & 1;
        int nr   = n & 7;
        Ws[(((kt * 2 + half) * 32) + nr * 4 + q) * 8 + sub * 4 + slot] = __float2half_rn(w);
    }

    // ---- per-thread constants ----
    float br[4][2];
    #pragma unroll
    for (int tg = 0; tg < 4; ++tg) {
        int col = tg * HH + j0 + ((lane & 3) << 1);
        br[tg][0] = bias[col];
        br[tg][1] = bias[col + 1];
    }
    float cst[4] = {0.f, 0.f, 0.f, 0.f};      // resident cell state

    uint32_t ab_shared = (uint32_t)__cvta_generic_to_shared(Ab);
    // ldmatrix per-thread address: row = warp*16 + (lane&15), col-block = (lane>>4)*8
    uint32_t lds_a_off = (uint32_t)(((warp * 16 + (lane & 15)) * AROW + ((lane >> 4) << 3)) * 2);
    const int R  = warp * 16 + (lane >> 2);   // batch row of c0/c1
    const int jc = j0 + ((lane & 3) << 1);    // hidden col of c0

    const int r0v  = tid / 48;                // staging cursor init (3072 vec / step-chunk)
    const int kv0v = tid - r0v * 48;

    const uint4* WsLane = (const uint4*)Ws + lane;  // + (kt*2+half)*32 per access
    const unsigned* my_ctr = &g_ctrs[lane & (NGRP - 1)].v;   // poll target
    unsigned* rel_ctr = &g_ctrs[cta & (NGRP - 1)].v;          // release target

    __syncthreads();

    for (int s = 1; s <= TT; ++s) {
        const int t  = s - 1;
        const int pr = (s - 1) & 1;           // read h_{s-1}
        const int pw = s & 1;                 // write h_s

        // ---- stage chunk 0 (pure x, no dependency on other CTAs) ----
        // Safe vs prior-step readers: every warp passed the h-publish barrier
        // of step s-1 before arriving here.
        {
            uint32_t dstb = ab_shared;
            int r = r0v, kv = kv0v;
            #pragma unroll
            for (int it = 0; it < 24; ++it) {
                const __half* src = g_xh + ((size_t)r * TT + t) * DD + kv * 8;
                cp16(dstb + (uint32_t)((r * AROW + kv * 8) * 2), src);
                kv += 32; r += 2;
                if (kv >= 48) { kv -= 48; ++r; }
            }
            asm volatile("cp.async.commit_group;\n");
        }

        // ---- warp-collective poll over 8 split counters ----
        // Lane l acquire-loads counter l&7; warp proceeds when ALL groups hit
        // 16*(s-1). Acquire on a counter syncs-with every release-RMW of its
        // 16 producer CTAs; requiring all 8 covers all 128 CTAs.
        {
            unsigned target = (unsigned)(16 * (s - 1));
            bool done;
            do {
                unsigned v;
                asm volatile("ld.acquire.gpu.u32 %0, [%1];" : "=r"(v) : "l"(my_ctr));
                done = __all_sync(0xffffffffu, v >= target);
            } while (!done);
        }

        float acc[4][4];
        #pragma unroll
        for (int tg = 0; tg < 4; ++tg) {
            acc[tg][0] = br[tg][0]; acc[tg][1] = br[tg][1];
            acc[tg][2] = br[tg][0]; acc[tg][3] = br[tg][1];
        }

        // ---- K-chunk pipeline: stage c+1 while mma on c ----
        #pragma unroll
        for (int c = 0; c < NCHUNK; ++c) {
            if (c + 1 < NCHUNK) {
                const int k0 = (c + 1) * KC;
                uint32_t dstb = ab_shared + (uint32_t)(((c + 1) & 1) * (BB * AROW * 2));
                int r = r0v, kv = kv0v;
                #pragma unroll
                for (int it = 0; it < 24; ++it) {
                    int gk = k0 + kv * 8;
                    const __half* src = (gk < DD)
                        ? (g_xh + ((size_t)r * TT + t) * DD + gk)
                        : (&g_hbuf[pr][r][gk - DD]);
                    cp16(dstb + (uint32_t)((r * AROW + kv * 8) * 2), src);
                    kv += 32; r += 2;
                    if (kv >= 48) { kv -= 48; ++r; }
                }
                asm volatile("cp.async.commit_group;\n");
                asm volatile("cp.async.wait_group 1;\n");
            } else {
                asm volatile("cp.async.wait_group 0;\n");
            }
            __syncthreads();

            // ---- mma over chunk c: warp = m16 tile, 4 n8 gate tiles, 24 k16 steps
            uint32_t abase = ab_shared + (uint32_t)((c & 1) * (BB * AROW * 2)) + lds_a_off;
            const int kt0 = c * 24;
            #pragma unroll 4
            for (int kt = 0; kt < 24; ++kt) {
                uint32_t a0, a1, a2, a3;
                asm volatile("ldmatrix.sync.aligned.m8n8.x4.shared.b16 {%0,%1,%2,%3}, [%4];"
                             : "=r"(a0), "=r"(a1), "=r"(a2), "=r"(a3)
                             : "r"(abase + (uint32_t)(kt * 32)));
                // one LDS.128 per gate-pair: {b0,b1}(tg=2h) in .x.y, (tg=2h+1) in .z.w
                uint4 v0 = WsLane[((kt0 + kt) * 2 + 0) * 32];
                uint4 v1 = WsLane[((kt0 + kt) * 2 + 1) * 32];
                asm volatile(
                    "mma.sync.aligned.m16n8k16.row.col.f32.f16.f16.f32 "
                    "{%0,%1,%2,%3}, {%4,%5,%6,%7}, {%8,%9}, {%0,%1,%2,%3};"
                    : "+f"(acc[0][0]), "+f"(acc[0][1]), "+f"(acc[0][2]), "+f"(acc[0][3])
                    : "r"(a0), "r"(a1), "r"(a2), "r"(a3), "r"(v0.x), "r"(v0.y));
                asm volatile(
                    "mma.sync.aligned.m16n8k16.row.col.f32.f16.f16.f32 "
                    "{%0,%1,%2,%3}, {%4,%5,%6,%7}, {%8,%9}, {%0,%1,%2,%3};"
                    : "+f"(acc[1][0]), "+f"(acc[1][1]), "+f"(acc[1][2]), "+f"(acc[1][3])
                    : "r"(a0), "r"(a1), "r"(a2), "r"(a3), "r"(v0.z), "r"(v0.w));
                asm volatile(
                    "mma.sync.aligned.m16n8k16.row.col.f32.f16.f16.f32 "
                    "{%0,%1,%2,%3}, {%4,%5,%6,%7}, {%8,%9}, {%0,%1,%2,%3};"
                    : "+f"(acc[2][0]), "+f"(acc[2][1]), "+f"(acc[2][2]), "+f"(acc[2][3])
                    : "r"(a0), "r"(a1), "r"(a2), "r"(a3), "r"(v1.x), "r"(v1.y));
                asm volatile(
                    "mma.sync.aligned.m16n8k16.row.col.f32.f16.f16.f32 "
                    "{%0,%1,%2,%3}, {%4,%5,%6,%7}, {%8,%9}, {%0,%1,%2,%3};"
                    : "+f"(acc[3][0]), "+f"(acc[3][1]), "+f"(acc[3][2]), "+f"(acc[3][3])
                    : "r"(a0), "r"(a1), "r"(a2), "r"(a3), "r"(v1.z), "r"(v1.w));
            }
            // Barrier B(c): protects buf[(c+1)&1] against restaging at iteration
            // c+1. Only iterations 1 and 2 stage; B(2)/B(3) are redundant —
            // next-step stagings are ordered behind the h-publish barrier.
            if (c < 2) __syncthreads();
        }

        // ---- elementwise LSTM cell update (all in registers) ----
        float hv[4];
        #pragma unroll
        for (int e = 0; e < 4; ++e) {
            float ig = sigf(acc[0][e]);
            float fg = sigf(acc[1][e]);
            float gg = tanhfast(acc[2][e]);
            float og = sigf(acc[3][e]);
            float cn = fg * cst[e] + ig * gg;
            cst[e] = cn;
            hv[e] = og * tanhfast(cn);
        }

        // ---- CRITICAL PATH: publish h_s and release as early as possible ----
        // The __syncthreads here is ALSO the per-step rendezvous that makes
        // next-step staging safe against this step's smem readers.
        if (s < TT) {
            *(__half2*)&g_hbuf[pw][R][jc]     = __floats2half2_rn(hv[0], hv[1]);
            *(__half2*)&g_hbuf[pw][R + 8][jc] = __floats2half2_rn(hv[2], hv[3]);
            __syncthreads();                  // all h-writes happen-before release
            if (tid == 0) {
                // release-reduction into this CTA's group counter
                asm volatile("red.release.gpu.global.add.u32 [%0], %1;"
                             :: "l"(rel_ctr), "r"(1u) : "memory");
            }
        }

        // ---- OFF critical path: fp32 output stores (consumed only at exit) ----
        __stcs((float2*)&out[((size_t)R * TT + t) * HH + jc],
               make_float2(hv[0], hv[1]));
        __stcs((float2*)&out[((size_t)(R + 8) * TT + t) * HH + jc],
               make_float2(hv[2], hv[3]));
    }
}

// ---------------------------------------------------------------------------
// Launch
// ---------------------------------------------------------------------------
extern "C" void kernel_launch(void* const* d_in, const int* in_sizes, int n_in,
                              void* d_out, int out_size)
{
    const float *inputs = nullptr, *Wxp = nullptr, *Whp = nullptr, *bp = nullptr;
    for (int i = 0; i < n_in; ++i) {
        int sz = in_sizes[i];
        if (sz == BB * TT * DD)      inputs = (const float*)d_in[i];
        else if (sz == DD * 4 * HH)  Wxp    = (const float*)d_in[i];
        else if (sz == HH * 4 * HH)  Whp    = (const float*)d_in[i];
        else if (sz == 4 * HH)       bp     = (const float*)d_in[i];
    }
    float* out = (float*)d_out;

    void *xh = nullptr, *hb = nullptr, *ctr = nullptr;
    cudaGetSymbolAddress(&xh, g_xh);
    cudaGetSymbolAddress(&hb, g_hbuf);
    cudaGetSymbolAddress(&ctr, g_ctrs);

    cudaFuncSetAttribute(lstm_kernel, cudaFuncAttributeMaxDynamicSharedMemorySize, SMEM_BYTES);

    // reset cross-launch state: h0 = 0 and progress counters = 0 (graph-capturable)
    cudaMemsetAsync(hb, 0, sizeof(__half) * 2 * BB * HH, 0);
    cudaMemsetAsync(ctr, 0, sizeof(CtrSlot) * NGRP, 0);

    cvt_kernel<<<1024, 256>>>(inputs, (__half2*)xh, (BB * TT * DD) / 4);
    lstm_kernel<<<NCTA, THREADS, SMEM_BYTES>>>(Wxp, Whp, bp, out);
    (void)out_size;
}